// round 9
// baseline (speedup 1.0000x reference)
#include <cuda_runtime.h>
#include <cuda_bf16.h>
#include <cstdint>

#define BB   4096      // batch rows
#define SEQ  2048      // sequence length S
#define SU   2056      // u row stride (S + E)
#define OUTW 2057      // out row stride (S + AR + 1)
#define KC   64        // chunk length
#define NCH  32        // chunks per row (SEQ / KC)
#define ORD  9         // recurrence order (AR + 1)
#define EX   8         // exogenous dim
#define BT   128       // b-rows per block in the two big passes

// Static device scratch (b-fastest layouts, coalesced for lane = b)
__device__ float g_v[NCH * ORD * BB];      // [m][k][b] zero-state final windows
__device__ float g_s[NCH * ORD * BB];      // [m][k][b] true boundary states

__device__ __forceinline__ void load_a(const float* __restrict__ W, float* a) {
    a[0] = -__ldg(&W[0]);
    #pragma unroll
    for (int k = 1; k < 8; k++) a[k] = __ldg(&W[k - 1]) - __ldg(&W[k]);
    a[8] = 1.0f + __ldg(&W[7]);
}

// One scalar recurrence step (17 FMA-class ops), compile-time rotation.
__device__ __forceinline__ float step_rec(const float* a, const float* wu,
                                          const float* uw, const float* w, int j) {
    float e0 = wu[0] * uw[(0 + j) % 9] + wu[1] * uw[(1 + j) % 9];
    float e1 = wu[2] * uw[(2 + j) % 9] + wu[3] * uw[(3 + j) % 9];
    float e2 = wu[4] * uw[(4 + j) % 9] + wu[5] * uw[(5 + j) % 9];
    float e3 = wu[6] * uw[(6 + j) % 9] + wu[7] * uw[(7 + j) % 9];
    float c  = (e0 + e1) + (e2 + e3);
    float s0 = c + a[0] * w[(0 + j) % 9];
    float s1 = a[1] * w[(1 + j) % 9] + a[2] * w[(2 + j) % 9];
    float s2 = a[3] * w[(3 + j) % 9] + a[4] * w[(4 + j) % 9];
    float s3 = a[5] * w[(5 + j) % 9] + a[6] * w[(6 + j) % 9];
    float x  = ((s0 + s1) + (s2 + s3)) + a[7] * w[(7 + j) % 9];
    return fmaf(a[8], w[(8 + j) % 9], x);
}

// Async phased tile load via cp.async (LDGSTS): register-free, full MLP.
// Cols [c0, c0+38] of this block's 128 u-rows into su[r][0..38].
__device__ __forceinline__ void load_utile_async(const float* __restrict__ u,
                                                 float (*su)[41],
                                                 int b0, int m, int c0,
                                                 int lane, int wr) {
    #pragma unroll
    for (int r = wr; r < BT; r += 4) {
        const float* ur = u + (size_t)(b0 + r) * SU + 1 + m * KC + c0;
        unsigned int d0 = (unsigned int)__cvta_generic_to_shared(&su[r][lane]);
        asm volatile("cp.async.ca.shared.global [%0], [%1], 4;"
                     :: "r"(d0), "l"(ur + lane));
        if (lane < 7) {
            unsigned int d1 = (unsigned int)__cvta_generic_to_shared(&su[r][lane + 32]);
            asm volatile("cp.async.ca.shared.global [%0], [%1], 4;"
                         :: "r"(d1), "l"(ur + lane + 32));
        }
    }
    asm volatile("cp.async.commit_group;" ::: "memory");
}
#define CP_WAIT_ALL() asm volatile("cp.async.wait_group 0;" ::: "memory")

// ---------------------------------------------------------------------------
// Kernel 1 (cv): zero-state recurrence per (chunk m, row b); 64 steps in two
// 32-step phases (21 KB smem). Emits final 9-window to g_v[m][k][b].
// ---------------------------------------------------------------------------
__global__ void __launch_bounds__(BT) cv_kernel(const float* __restrict__ u,
                                                const float* __restrict__ W) {
    __shared__ float su[BT][41];           // stride 41: gcd(41,32)=1, conflict-free
    int m  = blockIdx.x >> 5;
    int b0 = (blockIdx.x & 31) * BT;
    int tid = threadIdx.x;
    int lane = tid & 31, wr = tid >> 5;

    // Phase A load first (overlaps coef setup)
    load_utile_async(u, su, b0, m, 0, lane, wr);

    float a[ORD], wu[EX];
    load_a(W, a);
    #pragma unroll
    for (int e = 0; e < EX; e++) wu[e] = __ldg(&W[8 + e]);

    CP_WAIT_ALL();
    __syncthreads();

    float w[ORD], uw[ORD];
    #pragma unroll
    for (int k = 0; k < ORD; k++) { w[k] = 0.0f; uw[k] = su[tid][k]; }

    #pragma unroll
    for (int j = 0; j < 32; j++) {
        float x = step_rec(a, wu, uw, w, j);
        if (j <= 29) uw[j % 9] = su[tid][j + 9];   // cols 9..38
        w[j % 9] = x;
    }
    __syncthreads();

    // Phase B: cols 32..70 at su[tid][cc-32]
    load_utile_async(u, su, b0, m, 32, lane, wr);
    CP_WAIT_ALL();
    __syncthreads();
    uw[30 % 9] = su[tid][7];   // col 39 (deferred refill of step 30)
    uw[31 % 9] = su[tid][8];   // col 40 (deferred refill of step 31)

    #pragma unroll
    for (int j = 32; j < KC; j++) {
        float x = step_rec(a, wu, uw, w, j);
        if (j <= 61) uw[j % 9] = su[tid][j - 23];  // col j+9
        w[j % 9] = x;
    }

    float* gv = g_v + ((size_t)m * ORD) * BB + b0 + tid;
    #pragma unroll
    for (int k = 0; k < ORD; k++) gv[(size_t)k * BB] = w[(k + KC) % 9];
}

// ---------------------------------------------------------------------------
// Kernel 2 (states): M = A^K in registers via lane recurrences + shfl;
// 31-step boundary chain with 2-deep v prefetch. out[b][0..8] = y.
// ---------------------------------------------------------------------------
__global__ void __launch_bounds__(32) states_kernel(const float* __restrict__ W,
                                                    const float* __restrict__ y,
                                                    float* __restrict__ out) {
    int lane = threadIdx.x;
    int b = blockIdx.x * 32 + lane;

    float a[ORD];
    load_a(W, a);

    float w[ORD];
    #pragma unroll
    for (int k = 0; k < ORD; k++) w[k] = (k == lane) ? 1.0f : 0.0f;
    #pragma unroll
    for (int p = 0; p < KC; p++) {
        float z = 0.0f;
        #pragma unroll
        for (int k = 0; k < ORD; k++) z += a[k] * w[(k + p) % 9];
        w[p % 9] = z;
    }
    float MT[ORD * ORD];
    #pragma unroll
    for (int r = 0; r < ORD; r++)
        #pragma unroll
        for (int k = 0; k < ORD; k++)
            MT[r * ORD + k] = __shfl_sync(0xffffffffu, w[(k + KC) % 9], r);

    float s[ORD];
    #pragma unroll
    for (int k = 0; k < ORD; k++) {
        s[k] = y[(size_t)b * ORD + k];
        out[(size_t)b * OUTW + k] = s[k];
        g_s[(size_t)k * BB + b] = s[k];
    }

    float va[ORD], vb[ORD];
    #pragma unroll
    for (int k = 0; k < ORD; k++) va[k] = g_v[(size_t)k * BB + b];
    #pragma unroll
    for (int k = 0; k < ORD; k++) vb[k] = g_v[((size_t)ORD + k) * BB + b];

    #pragma unroll
    for (int m = 0; m < NCH - 1; m++) {
        float ns[ORD];
        #pragma unroll
        for (int k = 0; k < ORD; k++) ns[k] = va[k];
        #pragma unroll
        for (int k = 0; k < ORD; k++) va[k] = vb[k];
        if (m + 2 <= NCH - 2) {
            const float* gv = g_v + ((size_t)(m + 2) * ORD) * BB + b;
            #pragma unroll
            for (int k = 0; k < ORD; k++) vb[k] = gv[(size_t)k * BB];
        }
        #pragma unroll
        for (int r = 0; r < ORD; r++) {
            float sr = s[r];
            #pragma unroll
            for (int k = 0; k < ORD; k++) ns[k] += MT[r * ORD + k] * sr;
        }
        float* gs = g_s + ((size_t)(m + 1) * ORD) * BB + b;
        #pragma unroll
        for (int k = 0; k < ORD; k++) { s[k] = ns[k]; gs[(size_t)k * BB] = s[k]; }
    }
}

// ---------------------------------------------------------------------------
// Kernel 3 (pass2): true-state replay, two-phase cp.async u tile; stages 16
// steps in smem and flushes to out in coalesced 64B row segments.
// ---------------------------------------------------------------------------
__global__ void __launch_bounds__(BT) pass2_kernel(const float* __restrict__ u,
                                                   const float* __restrict__ W,
                                                   float* __restrict__ out) {
    __shared__ float su[BT][41];
    __shared__ float sb[16][BT + 1];
    int m  = blockIdx.x >> 5;
    int b0 = (blockIdx.x & 31) * BT;
    int tid = threadIdx.x;
    int lane = tid & 31, wr = tid >> 5;
    int ocol0 = ORD + m * KC;

    load_utile_async(u, su, b0, m, 0, lane, wr);

    float a[ORD], wu[EX];
    load_a(W, a);
    #pragma unroll
    for (int e = 0; e < EX; e++) wu[e] = __ldg(&W[8 + e]);

    float w[ORD], uw[ORD];
    const float* gs = g_s + ((size_t)m * ORD) * BB + b0 + tid;
    #pragma unroll
    for (int k = 0; k < ORD; k++) w[k] = gs[(size_t)k * BB];

    CP_WAIT_ALL();
    __syncthreads();
    #pragma unroll
    for (int k = 0; k < ORD; k++) uw[k] = su[tid][k];

    #pragma unroll
    for (int j = 0; j < 32; j++) {
        float x = step_rec(a, wu, uw, w, j);
        if (j <= 29) uw[j % 9] = su[tid][j + 9];
        w[j % 9] = x;
        sb[j & 15][tid] = x;
        if ((j & 15) == 15) {
            __syncthreads();
            int jj = j & ~15;
            #pragma unroll
            for (int q = 0; q < 16; q++) {
                int e  = q * BT + tid;
                int tp = e & 15;
                int bp = e >> 4;
                out[(size_t)(b0 + bp) * OUTW + ocol0 + jj + tp] = sb[tp][bp];
            }
            __syncthreads();
        }
    }

    load_utile_async(u, su, b0, m, 32, lane, wr);
    CP_WAIT_ALL();
    __syncthreads();
    uw[30 % 9] = su[tid][7];   // col 39
    uw[31 % 9] = su[tid][8];   // col 40

    #pragma unroll
    for (int j = 32; j < KC; j++) {
        float x = step_rec(a, wu, uw, w, j);
        if (j <= 61) uw[j % 9] = su[tid][j - 23];
        w[j % 9] = x;
        sb[j & 15][tid] = x;
        if ((j & 15) == 15) {
            __syncthreads();
            int jj = j & ~15;
            #pragma unroll
            for (int q = 0; q < 16; q++) {
                int e  = q * BT + tid;
                int tp = e & 15;
                int bp = e >> 4;
                out[(size_t)(b0 + bp) * OUTW + ocol0 + jj + tp] = sb[tp][bp];
            }
            __syncthreads();
        }
    }
}

// ---------------------------------------------------------------------------
extern "C" void kernel_launch(void* const* d_in, const int* in_sizes, int n_in,
                              void* d_out, int out_size) {
    const float* y = (const float*)d_in[0];
    const float* u = (const float*)d_in[1];
    const float* W = (const float*)d_in[2];
    for (int i = 0; i < n_in; i++) {
        if (in_sizes[i] == BB * ORD)      y = (const float*)d_in[i];
        else if (in_sizes[i] == BB * SU)  u = (const float*)d_in[i];
        else if (in_sizes[i] == 16)       W = (const float*)d_in[i];
    }
    float* out = (float*)d_out;

    cudaFuncSetAttribute(cv_kernel,    cudaFuncAttributePreferredSharedMemoryCarveout, 100);
    cudaFuncSetAttribute(pass2_kernel, cudaFuncAttributePreferredSharedMemoryCarveout, 100);

    cv_kernel<<<NCH * (BB / BT), BT>>>(u, W);       // 1024 x 128
    states_kernel<<<BB / 32, 32>>>(W, y, out);      // 128 x 32
    pass2_kernel<<<NCH * (BB / BT), BT>>>(u, W, out);
}